// round 2
// baseline (speedup 1.0000x reference)
#include <cuda_runtime.h>

#define NN 4096
#define HH 64
#define HIK 8
#define NSPLIT 16
#define CHUNK 256     // NN / NSPLIT
#define IBLK 256
#define EPSF 1e-8f

// Deterministic partial-force scratch: [NSPLIT][NN][3]
__device__ float g_partial[NSPLIT * NN * 3];

// ---------------------------------------------------------------------------
// Kernel A: per-particle MLP.  4 threads per particle, each handles 16 of the
// 64 hidden units, shuffle-reduce across the 4 lanes.  Writes:
//   out[0 .. 3N)   = v (base of dz_dt; forces added later)
//   out[3N .. 4N)  = grow (dlnw_dt)
//   out[4N .. 5N)  = (|v|^2 + grow^2) * exp(lnw)   (dm_dt)
// ---------------------------------------------------------------------------
__global__ void mlp_kernel(const float* __restrict__ t,
                           const float* __restrict__ z,
                           const float* __restrict__ lnw,
                           const float* __restrict__ W1,
                           const float* __restrict__ b1,
                           const float* __restrict__ Wv,
                           const float* __restrict__ bv,
                           const float* __restrict__ Wg,
                           const float* __restrict__ bg,
                           float* __restrict__ out) {
    __shared__ float sW1[4 * HH];   // (D+1, H) row-major
    __shared__ float sWv[HH * 3];   // (H, 3)   row-major
    __shared__ float sWg[HH];
    __shared__ float sb1[HH];

    int tid = threadIdx.x;
    for (int k = tid; k < 4 * HH; k += blockDim.x) sW1[k] = W1[k];
    for (int k = tid; k < HH * 3; k += blockDim.x) sWv[k] = Wv[k];
    if (tid < HH) { sWg[tid] = Wg[tid]; sb1[tid] = b1[tid]; }
    __syncthreads();

    int idx = blockIdx.x * blockDim.x + tid;   // 4 * NN threads total
    int i = idx >> 2;
    int q = idx & 3;

    float z0 = z[i * 3 + 0];
    float z1 = z[i * 3 + 1];
    float z2 = z[i * 3 + 2];
    float tv = t[0];

    float v0 = 0.f, v1 = 0.f, v2 = 0.f, g = 0.f;
    int k0 = q * 16;
#pragma unroll
    for (int kk = 0; kk < 16; ++kk) {
        int k = k0 + kk;
        float a = fmaf(z0, sW1[k],
                  fmaf(z1, sW1[HH + k],
                  fmaf(z2, sW1[2 * HH + k],
                  fmaf(tv, sW1[3 * HH + k], sb1[k]))));
        float h = tanhf(a);
        v0 = fmaf(h, sWv[k * 3 + 0], v0);
        v1 = fmaf(h, sWv[k * 3 + 1], v1);
        v2 = fmaf(h, sWv[k * 3 + 2], v2);
        g  = fmaf(h, sWg[k], g);
    }

    // reduce across the 4 lanes sharing a particle (contiguous lanes in warp)
#pragma unroll
    for (int off = 1; off < 4; off <<= 1) {
        v0 += __shfl_xor_sync(0xFFFFFFFFu, v0, off);
        v1 += __shfl_xor_sync(0xFFFFFFFFu, v1, off);
        v2 += __shfl_xor_sync(0xFFFFFFFFu, v2, off);
        g  += __shfl_xor_sync(0xFFFFFFFFu, g,  off);
    }

    if (q == 0) {
        v0 += bv[0]; v1 += bv[1]; v2 += bv[2];
        g  += bg[0];
        out[i * 3 + 0] = v0;
        out[i * 3 + 1] = v1;
        out[i * 3 + 2] = v2;
        out[3 * NN + i] = g;
        float w = expf(lnw[i]);
        out[4 * NN + i] = (v0 * v0 + v1 * v1 + v2 * v2 + g * g) * w;
    }
}

// ---------------------------------------------------------------------------
// Kernel B: pairwise force, tiled.  Block (ib, s): particles i in
// [ib*256, ib*256+256), neighbors j in [s*256, s*256+256) staged in smem as
// float4 (zx, zy, zz, exp(lnw)).  Cheap distance pass builds a 64-bit
// survivor bitmask per 64-j subchunk; the expensive U'(r) evaluation only
// runs on set bits (~1.2% of pairs).  Partial forces go to g_partial.
// ---------------------------------------------------------------------------
__global__ void force_kernel(const float* __restrict__ z,
                             const float* __restrict__ lnw,
                             const float* __restrict__ Wi1,
                             const float* __restrict__ bi1,
                             const float* __restrict__ Wi2) {
    __shared__ float4 zsh[CHUNK];

    int tid = threadIdx.x;
    int ib = blockIdx.x;
    int s  = blockIdx.y;
    int jbase = s * CHUNK;

    {
        int jg = jbase + tid;
        zsh[tid] = make_float4(z[jg * 3 + 0], z[jg * 3 + 1], z[jg * 3 + 2],
                               expf(lnw[jg]));
    }

    float wi1[HIK], bb[HIK], cc[HIK];
#pragma unroll
    for (int k = 0; k < HIK; ++k) {
        wi1[k] = Wi1[k];
        bb[k]  = bi1[k];
        cc[k]  = wi1[k] * Wi2[k];
    }
    __syncthreads();

    int i = ib * IBLK + tid;
    float zx = z[i * 3 + 0];
    float zy = z[i * 3 + 1];
    float zz = z[i * 3 + 2];

    float fx = 0.f, fy = 0.f, fz = 0.f;
    bool diag = (ib == s);

#pragma unroll 1
    for (int jb = 0; jb < CHUNK / 64; ++jb) {
        unsigned long long m = 0ull;
#pragma unroll 8
        for (int jj = 0; jj < 64; ++jj) {
            float4 zj = zsh[jb * 64 + jj];
            float dx = zx - zj.x;
            float dy = zy - zj.y;
            float dz = zz - zj.z;
            float d2 = fmaf(dx, dx, EPSF);
            d2 = fmaf(dy, dy, d2);
            d2 = fmaf(dz, dz, d2);
            // branch-free predicated bit set: dist < 0.5 <=> d2 < 0.25
            m |= (d2 < 0.25f) ? (1ull << jj) : 0ull;
        }
        // remove self-pair (only possible on the diagonal block)
        if (diag && ((tid >> 6) == jb)) m &= ~(1ull << (tid & 63));

        while (m) {
            int b = __ffsll((long long)m) - 1;
            m &= (m - 1);
            float4 zj = zsh[jb * 64 + b];
            float dx = zx - zj.x;
            float dy = zy - zj.y;
            float dz = zz - zj.z;
            float d2 = fmaf(dx, dx, EPSF);
            d2 = fmaf(dy, dy, d2);
            d2 = fmaf(dz, dz, d2);
            float rd   = rsqrtf(d2);
            float dist = d2 * rd;            // sqrt(d2)
            float dU = 0.f;
#pragma unroll
            for (int k = 0; k < HIK; ++k) {
                float th = tanhf(fmaf(dist, wi1[k], bb[k]));
                dU = fmaf(fmaf(-th, th, 1.0f), cc[k], dU);
            }
            // coeff = -(w_j * dU / dist) / 16
            float coeff = dU * zj.w * rd * (-1.0f / 16.0f);
            fx = fmaf(coeff, dx, fx);
            fy = fmaf(coeff, dy, fy);
            fz = fmaf(coeff, dz, fz);
        }
    }

    float* p = &g_partial[(size_t)(s * NN + i) * 3];
    p[0] = fx;
    p[1] = fy;
    p[2] = fz;
}

// ---------------------------------------------------------------------------
// Kernel C: deterministic reduction of the NSPLIT partial forces into dz_dt.
// ---------------------------------------------------------------------------
__global__ void reduce_kernel(float* __restrict__ out) {
    int idx = blockIdx.x * blockDim.x + threadIdx.x;   // < NN*3
    float acc = 0.f;
#pragma unroll
    for (int s = 0; s < NSPLIT; ++s) acc += g_partial[s * (NN * 3) + idx];
    out[idx] += acc;
}

extern "C" void kernel_launch(void* const* d_in, const int* in_sizes, int n_in,
                              void* d_out, int out_size) {
    (void)in_sizes; (void)n_in; (void)out_size;
    const float* t   = (const float*)d_in[0];
    const float* z   = (const float*)d_in[1];
    const float* lnw = (const float*)d_in[2];
    const float* W1  = (const float*)d_in[3];
    const float* b1  = (const float*)d_in[4];
    const float* Wv  = (const float*)d_in[5];
    const float* bv  = (const float*)d_in[6];
    const float* Wg  = (const float*)d_in[7];
    const float* bg  = (const float*)d_in[8];
    const float* Wi1 = (const float*)d_in[9];
    const float* bi1 = (const float*)d_in[10];
    const float* Wi2 = (const float*)d_in[11];
    // d_in[12] = bi2: only shifts U, not dU/dr -> unused
    float* out = (float*)d_out;

    mlp_kernel<<<(NN * 4) / 256, 256>>>(t, z, lnw, W1, b1, Wv, bv, Wg, bg, out);
    force_kernel<<<dim3(NN / IBLK, NSPLIT), IBLK>>>(z, lnw, Wi1, bi1, Wi2);
    reduce_kernel<<<(NN * 3) / 256, 256>>>(out);
}

// round 3
// speedup vs baseline: 1.5662x; 1.5662x over previous
#include <cuda_runtime.h>

#define NN 4096
#define HH 64
#define HIK 8
#define NSPLIT 32
#define CHUNK 128            // j-chunk per force block
#define IBLK 128             // i-rows / threads per force block
#define NIB (NN / IBLK)      // 32
#define NFORCE (NSPLIT * NIB)        // 1024 force blocks
#define NMLP ((NN * 8) / 128)        // 256 mlp blocks (8 threads/particle)
#define TBL 1024
#define EPSF 1e-8f

// Deterministic partial-force scratch: [NSPLIT][NN][3]
__device__ float g_partial[NSPLIT * NN * 3];
// dU(r) lookup table on [0, 0.5): {value, delta-to-next}
__device__ float2 g_table[TBL];

// ---------------------------------------------------------------------------
// Setup: tabulate dU(r) = sum_k Wi1[k]*Wi2[k]*(1 - tanh(r*Wi1[k]+bi1[k])^2)
// at 1024 bins over [0, 0.5).  Linear-interp error ~1e-6 absolute.
// ---------------------------------------------------------------------------
__global__ void setup_kernel(const float* __restrict__ Wi1,
                             const float* __restrict__ bi1,
                             const float* __restrict__ Wi2) {
    int i = blockIdx.x * blockDim.x + threadIdx.x;
    if (i >= TBL) return;
    const float h = 0.5f / (float)TBL;
    float r0 = (float)i * h;
    float r1 = (float)(i + 1) * h;
    float d0 = 0.f, d1 = 0.f;
#pragma unroll
    for (int k = 0; k < HIK; ++k) {
        float w = Wi1[k], b = bi1[k], c = w * Wi2[k];
        float t0 = tanhf(fmaf(r0, w, b));
        float t1 = tanhf(fmaf(r1, w, b));
        d0 = fmaf(fmaf(-t0, t0, 1.0f), c, d0);
        d1 = fmaf(fmaf(-t1, t1, 1.0f), c, d1);
    }
    g_table[i] = make_float2(d0, d1 - d0);
}

// fast tanh via exp: rel error ~1e-6, no branches
__device__ __forceinline__ float fast_tanh(float x) {
    x = fminf(fmaxf(x, -15.0f), 15.0f);
    float u = __expf(2.0f * x);
    return __fdividef(u - 1.0f, u + 1.0f);
}

// ---------------------------------------------------------------------------
// Fused kernel.
//   Blocks [0, NFORCE): pairwise force tiles (i-block x j-chunk).
//     Cheap prefilter (dot-product form, widened threshold) builds a 64-bit
//     survivor mask; survivor path recomputes exact d2 (difference form,
//     identical to reference semantics) and uses the dU table.
//   Blocks [NFORCE, NFORCE+NMLP): per-particle MLP, 8 threads/particle.
// ---------------------------------------------------------------------------
__global__ void fused_kernel(const float* __restrict__ t,
                             const float* __restrict__ z,
                             const float* __restrict__ lnw,
                             const float* __restrict__ W1,
                             const float* __restrict__ b1,
                             const float* __restrict__ Wv,
                             const float* __restrict__ bv,
                             const float* __restrict__ Wg,
                             const float* __restrict__ bg,
                             float* __restrict__ out) {
    int bx = blockIdx.x;
    int tid = threadIdx.x;

    if (bx < NFORCE) {
        // ------------------------- force role -------------------------
        __shared__ float4 zsh[CHUNK];   // (x, y, z, |z|^2)
        __shared__ float  wsh[CHUNK];   // exp(lnw_j)
        __shared__ float2 tbl[TBL];

        int s  = bx >> 5;    // j-chunk  0..31
        int ib = bx & 31;    // i-block  0..31

        {
            int jg = s * CHUNK + tid;
            float x = z[jg * 3 + 0];
            float y = z[jg * 3 + 1];
            float w = z[jg * 3 + 2];
            zsh[tid] = make_float4(x, y, w, x * x + y * y + w * w);
            wsh[tid] = expf(lnw[jg]);
        }
        {
            float4* td = (float4*)tbl;
            const float4* ts = (const float4*)g_table;
#pragma unroll
            for (int k = 0; k < (TBL / 2) / IBLK; ++k)
                td[tid + k * IBLK] = ts[tid + k * IBLK];
        }
        __syncthreads();

        int i = ib * IBLK + tid;
        float zx = z[i * 3 + 0];
        float zy = z[i * 3 + 1];
        float zz = z[i * 3 + 2];
        float ax = -2.0f * zx, ay = -2.0f * zy, az = -2.0f * zz;
        // prefilter (widened): |zj|^2 - 2 zi.zj < 0.25 + margin - |zi|^2
        float thr = 0.25f + 1e-4f - (zx * zx + zy * zy + zz * zz);

        float fx = 0.f, fy = 0.f, fz = 0.f;
        bool diag = (ib == s);

#pragma unroll 1
        for (int jb = 0; jb < CHUNK / 64; ++jb) {
            unsigned long long m = 0ull;
#pragma unroll
            for (int jj = 0; jj < 64; ++jj) {
                float4 zj = zsh[jb * 64 + jj];
                float d = fmaf(az, zj.z, zj.w);
                d = fmaf(ay, zj.y, d);
                d = fmaf(ax, zj.x, d);
                m |= (d < thr) ? (1ull << jj) : 0ull;
            }
            if (diag && ((tid >> 6) == jb)) m &= ~(1ull << (tid & 63));

            while (m) {
                int b = __ffsll((long long)m) - 1;
                m &= (m - 1);
                int j = jb * 64 + b;
                float4 zj = zsh[j];
                float dx = zx - zj.x;
                float dy = zy - zj.y;
                float dz = zz - zj.z;
                float d2 = fmaf(dx, dx, EPSF);   // exact (reference) form
                d2 = fmaf(dy, dy, d2);
                d2 = fmaf(dz, dz, d2);
                float rd = rsqrtf(d2);
                float r  = d2 * rd;              // sqrt(d2)
                float u  = r * (float)(2 * TBL); // bin width 0.5/1024
                int  iu  = (int)u;
                iu = (iu < TBL - 1) ? iu : (TBL - 1);
                float fr = u - (float)iu;
                float2 e = tbl[iu];
                float dU = fmaf(fr, e.y, e.x);
                float coeff = dU * wsh[j] * rd * (-1.0f / 16.0f);
                coeff = (d2 < 0.25f) ? coeff : 0.0f;  // exact mask decision
                fx = fmaf(coeff, dx, fx);
                fy = fmaf(coeff, dy, fy);
                fz = fmaf(coeff, dz, fz);
            }
        }

        float* p = &g_partial[((size_t)s * NN + (size_t)i) * 3];
        p[0] = fx;
        p[1] = fy;
        p[2] = fz;
    } else {
        // -------------------------- mlp role --------------------------
        __shared__ float sW1[4 * HH];   // (D+1, H) row-major
        __shared__ float sWv[HH * 3];
        __shared__ float sWg[HH];
        __shared__ float sb1[HH];

        int mb = bx - NFORCE;
        for (int k = tid; k < 4 * HH; k += 128) sW1[k] = W1[k];
        for (int k = tid; k < HH * 3; k += 128) sWv[k] = Wv[k];
        if (tid < HH) { sWg[tid] = Wg[tid]; sb1[tid] = b1[tid]; }
        __syncthreads();

        int idx = mb * 128 + tid;   // 8 * NN threads total
        int i = idx >> 3;
        int q = idx & 7;

        float z0 = z[i * 3 + 0];
        float z1 = z[i * 3 + 1];
        float z2 = z[i * 3 + 2];
        float tv = t[0];

        float v0 = 0.f, v1 = 0.f, v2 = 0.f, g = 0.f;
        int k0 = q * 8;
#pragma unroll
        for (int kk = 0; kk < 8; ++kk) {
            int k = k0 + kk;
            float a = fmaf(z0, sW1[k],
                      fmaf(z1, sW1[HH + k],
                      fmaf(z2, sW1[2 * HH + k],
                      fmaf(tv, sW1[3 * HH + k], sb1[k]))));
            float hh = fast_tanh(a);
            v0 = fmaf(hh, sWv[k * 3 + 0], v0);
            v1 = fmaf(hh, sWv[k * 3 + 1], v1);
            v2 = fmaf(hh, sWv[k * 3 + 2], v2);
            g  = fmaf(hh, sWg[k], g);
        }

#pragma unroll
        for (int off = 1; off < 8; off <<= 1) {
            v0 += __shfl_xor_sync(0xFFFFFFFFu, v0, off);
            v1 += __shfl_xor_sync(0xFFFFFFFFu, v1, off);
            v2 += __shfl_xor_sync(0xFFFFFFFFu, v2, off);
            g  += __shfl_xor_sync(0xFFFFFFFFu, g,  off);
        }

        if (q == 0) {
            v0 += bv[0]; v1 += bv[1]; v2 += bv[2];
            g  += bg[0];
            out[i * 3 + 0] = v0;
            out[i * 3 + 1] = v1;
            out[i * 3 + 2] = v2;
            out[3 * NN + i] = g;
            float w = expf(lnw[i]);
            out[4 * NN + i] = (v0 * v0 + v1 * v1 + v2 * v2 + g * g) * w;
        }
    }
}

// ---------------------------------------------------------------------------
// Deterministic reduction of the NSPLIT partial forces into dz_dt.
// ---------------------------------------------------------------------------
__global__ void reduce_kernel(float* __restrict__ out) {
    int idx = blockIdx.x * blockDim.x + threadIdx.x;   // < NN*3
    float acc = 0.f;
#pragma unroll
    for (int s = 0; s < NSPLIT; ++s) acc += g_partial[s * (NN * 3) + idx];
    out[idx] += acc;
}

extern "C" void kernel_launch(void* const* d_in, const int* in_sizes, int n_in,
                              void* d_out, int out_size) {
    (void)in_sizes; (void)n_in; (void)out_size;
    const float* t   = (const float*)d_in[0];
    const float* z   = (const float*)d_in[1];
    const float* lnw = (const float*)d_in[2];
    const float* W1  = (const float*)d_in[3];
    const float* b1  = (const float*)d_in[4];
    const float* Wv  = (const float*)d_in[5];
    const float* bv  = (const float*)d_in[6];
    const float* Wg  = (const float*)d_in[7];
    const float* bg  = (const float*)d_in[8];
    const float* Wi1 = (const float*)d_in[9];
    const float* bi1 = (const float*)d_in[10];
    const float* Wi2 = (const float*)d_in[11];
    // d_in[12] = bi2: only shifts U, not dU/dr -> unused
    float* out = (float*)d_out;

    setup_kernel<<<8, 128>>>(Wi1, bi1, Wi2);
    fused_kernel<<<NFORCE + NMLP, 128>>>(t, z, lnw, W1, b1, Wv, bv, Wg, bg, out);
    reduce_kernel<<<(NN * 3) / 128, 128>>>(out);
}